// round 16
// baseline (speedup 1.0000x reference)
#include <cuda_runtime.h>
#include <cuda_fp16.h>
#include <cstdint>

#define N_NODES 100000
#define N_EDGES 1600000
#define N_GRAPHS 512
#define N_REL 4
#define N_TYPES 13
#define HID 128
#define WCOLS 640            // logical K: [self(128) | rel0..3 (4*128)]
#define GCOLS 512            // stored aggregate cols (self removed)
#define BN_EPS 1e-5f
#define L2_EPS 1e-12f
#define NB_SCAN ((N_NODES + 255) / 256)   // 391

// ---------------- device scratch ---------------------------------------------
__device__ __align__(16) float  g_hA[N_NODES * HID];           // layer-0 pre-BN (fp32)
__device__ __align__(16) __half g_hF[N_NODES * HID];           // layer-0 post-BN (fp16)
__device__ __align__(16) __half g_hBh[N_NODES * HID];          // layer-1 GEMM out (fp16)
__device__ __align__(16) __half g_G[(size_t)N_NODES * GCOLS];  // per-rel aggregates (fp16)
__device__ __align__(16) float  g_T0[N_TYPES * WCOLS];
__device__ __align__(16) __half g_W1h[128 * WCOLS];            // packed weights, [n][k] fp16
__device__ int    g_ntype[N_NODES];
__device__ int    g_cnt4[N_NODES * 4];
__device__ float  g_winv[N_NODES * 4];
__device__ int    g_offs[N_NODES + 1];
__device__ int    g_cursor[N_NODES];
__device__ int    g_bsum[NB_SCAN];
__device__ int    g_bpre[NB_SCAN];
__device__ int    g_elist[N_EDGES];                            // packed (src<<6)|(ts<<2)|et
__device__ double g_stats[512];   // [0:128) sum0 [128:256) sq0 [256:384) sum1 [384:512) sq1
__device__ __align__(16) float g_pool[N_GRAPHS * HID];
__device__ int    g_gcnt[N_GRAPHS];

// ---------------- prep: zero accumulators + node types ------------------------
__global__ void k_prep(const float* __restrict__ x) {
    int i = blockIdx.x * blockDim.x + threadIdx.x;
    if (i < N_NODES * 4) g_cnt4[i] = 0;
    if (i < 512) g_stats[i] = 0.0;
    if (i < N_GRAPHS * HID) g_pool[i] = 0.f;
    if (i < N_GRAPHS) g_gcnt[i] = 0;
    if (i < N_NODES) {
        const float* row = x + (size_t)i * N_TYPES;
        int t = 0; float best = row[0];
        #pragma unroll
        for (int q = 1; q < N_TYPES; q++) {
            float v = row[q];
            if (v > best) { best = v; t = q; }
        }
        g_ntype[i] = t;
    }
}

// ---------------- per-(dst,rel) in-degree counts ------------------------------
__global__ void k_count(const int* __restrict__ ei, const int* __restrict__ etype) {
    int e = blockIdx.x * blockDim.x + threadIdx.x;
    if (e >= N_EDGES) return;
    int dst = ei[N_EDGES + e];
    int et  = etype[e];
    atomicAdd(&g_cnt4[dst * 4 + et], 1);
}

// ---------------- parallel scan, phase 1: block-local (+ winv) ----------------
__global__ void k_scan1() {
    __shared__ int sh[256];
    int tid = threadIdx.x;
    int i = blockIdx.x * 256 + tid;
    int d = 0;
    if (i < N_NODES) {
        int c0 = g_cnt4[4*i+0], c1 = g_cnt4[4*i+1];
        int c2 = g_cnt4[4*i+2], c3 = g_cnt4[4*i+3];
        d = c0 + c1 + c2 + c3;
        g_winv[4*i+0] = 1.f / fmaxf((float)c0, 1.f);
        g_winv[4*i+1] = 1.f / fmaxf((float)c1, 1.f);
        g_winv[4*i+2] = 1.f / fmaxf((float)c2, 1.f);
        g_winv[4*i+3] = 1.f / fmaxf((float)c3, 1.f);
    }
    sh[tid] = d;
    __syncthreads();
    #pragma unroll
    for (int off = 1; off < 256; off <<= 1) {
        int t = (tid >= off) ? sh[tid - off] : 0;
        __syncthreads();
        sh[tid] += t;
        __syncthreads();
    }
    if (i < N_NODES) g_offs[i] = sh[tid] - d;          // block-local exclusive
    if (tid == 255) g_bsum[blockIdx.x] = sh[255];
}

// ---------------- phase 2: scan block sums (1 block) ---------------------------
__global__ void k_scan2() {
    __shared__ int sh[512];
    int tid = threadIdx.x;
    int v = (tid < NB_SCAN) ? g_bsum[tid] : 0;
    sh[tid] = v;
    __syncthreads();
    #pragma unroll
    for (int off = 1; off < 512; off <<= 1) {
        int t = (tid >= off) ? sh[tid - off] : 0;
        __syncthreads();
        sh[tid] += t;
        __syncthreads();
    }
    if (tid < NB_SCAN) g_bpre[tid] = sh[tid] - v;      // exclusive
}

// ---------------- phase 3: add base, emit cursor -------------------------------
__global__ void k_scan3() {
    int i = blockIdx.x * blockDim.x + threadIdx.x;
    if (i < N_NODES) {
        int o = g_offs[i] + g_bpre[i >> 8];
        g_offs[i] = o;
        g_cursor[i] = o;
    }
    if (i == 0) g_offs[N_NODES] = N_EDGES;
}

// ---------------- fill CSR edge list (packs src type) ---------------------------
__global__ void k_fill(const int* __restrict__ ei, const int* __restrict__ etype) {
    int e = blockIdx.x * blockDim.x + threadIdx.x;
    if (e >= N_EDGES) return;
    int src = ei[e];
    int dst = ei[N_EDGES + e];
    int et  = etype[e];
    int ts  = g_ntype[src];
    int pos = atomicAdd(&g_cursor[dst], 1);
    g_elist[pos] = (src << 6) | (ts << 2) | et;
}

// ---------------- weights: layer-0 table + transposed fp16 layer-1 weights ------
__global__ void k_weights(const float* __restrict__ emb, const float* __restrict__ Wrel,
                          const float* __restrict__ Wroot, const float* __restrict__ bias) {
    int i = blockIdx.x * blockDim.x + threadIdx.x;
    if (i < N_TYPES * WCOLS) {
        int t = i / WCOLS, c = i % WCOLS;
        float s;
        if (c < 128) {
            s = bias[c];
            #pragma unroll 8
            for (int k = 0; k < 128; k++) s += emb[t*128 + k] * Wroot[k*128 + c];
        } else {
            int r = (c - 128) >> 7, j = (c - 128) & 127;
            const float* wr = Wrel + r * 16384;
            s = 0.f;
            #pragma unroll 8
            for (int k = 0; k < 128; k++) s += emb[t*128 + k] * wr[k*128 + j];
        }
        g_T0[i] = s;
    }
    int w = i - N_TYPES * WCOLS;
    if (w >= 0 && w < WCOLS * 128) {
        int kk = w / 128, c = w % 128;
        float v;
        if (kk < 128) v = Wroot[16384 + kk*128 + c];
        else {
            int r = (kk - 128) >> 7, k = (kk - 128) & 127;
            v = Wrel[(4 + r) * 16384 + k*128 + c];
        }
        g_W1h[c * WCOLS + kk] = __float2half_rn(v);   // transposed [n][k]
    }
}

// ---------------- layer-0 aggregation: elist stream + L1 table → g_hA (f32) -----
__global__ __launch_bounds__(256) void k_agg0() {
    int node = (blockIdx.x * 256 + threadIdx.x) >> 5;
    int lane = threadIdx.x & 31;
    if (node >= N_NODES) return;
    float w0 = g_winv[node*4+0], w1 = g_winv[node*4+1];
    float w2 = g_winv[node*4+2], w3 = g_winv[node*4+3];
    float4 acc = *reinterpret_cast<const float4*>(&g_T0[g_ntype[node] * WCOLS + lane * 4]);
    int beg = g_offs[node], end = g_offs[node + 1];

    auto addw = [&](int et, float4 m) {
        float w = (et == 0) ? w0 : (et == 1) ? w1 : (et == 2) ? w2 : w3;
        acc.x += m.x * w; acc.y += m.y * w; acc.z += m.z * w; acc.w += m.w * w;
    };
    auto t0row = [&](int p) -> const float4* {
        int ts = (p >> 2) & 15, et = p & 3;
        return reinterpret_cast<const float4*>(&g_T0[ts * WCOLS + 128 + et * 128 + lane * 4]);
    };

    int e = beg;
    for (; e + 4 <= end; e += 4) {
        int p0 = g_elist[e], p1 = g_elist[e+1], p2 = g_elist[e+2], p3 = g_elist[e+3];
        float4 m0 = *t0row(p0);
        float4 m1 = *t0row(p1);
        float4 m2 = *t0row(p2);
        float4 m3 = *t0row(p3);
        addw(p0 & 3, m0); addw(p1 & 3, m1); addw(p2 & 3, m2); addw(p3 & 3, m3);
    }
    for (; e < end; e++) {
        int p = g_elist[e];
        float4 m = *t0row(p);
        addw(p & 3, m);
    }
    *reinterpret_cast<float4*>(&g_hA[(size_t)node * 128 + lane * 4]) = acc;
}

// ---------------- BN stats layer 0 (separate pass: 512 atomics/address) ---------
__global__ void k_bnstats0() {
    int col = threadIdx.x;             // 128 threads
    double s = 0.0, s2 = 0.0;
    for (int r = blockIdx.x; r < N_NODES; r += gridDim.x) {
        float v = g_hA[(size_t)r * 128 + col];
        s  += (double)v;
        s2 += (double)v * (double)v;
    }
    atomicAdd(&g_stats[col], s);
    atomicAdd(&g_stats[128 + col], s2);
}

// ---------------- BN apply + PReLU + L2norm: g_hA (f32) → g_hF (fp16) only ------
__global__ __launch_bounds__(256) void k_bnapply0(const float* __restrict__ gamma,
                                                  const float* __restrict__ beta,
                                                  const float* __restrict__ pa) {
    int node = (blockIdx.x * 256 + threadIdx.x) >> 5;
    int lane = threadIdx.x & 31;
    if (node >= N_NODES) return;
    float alpha = pa[0];
    float4 v = *reinterpret_cast<const float4*>(&g_hA[(size_t)node * 128 + lane * 4]);
    float vin[4] = { v.x, v.y, v.z, v.w };
    float y[4]; float ss = 0.f;
    #pragma unroll
    for (int q = 0; q < 4; q++) {
        int c = lane * 4 + q;
        double mu  = g_stats[c] * (1.0 / N_NODES);
        double var = g_stats[128 + c] * (1.0 / N_NODES) - mu * mu;
        float sc = rsqrtf((float)var + BN_EPS) * gamma[c];
        float val = (vin[q] - (float)mu) * sc + beta[c];
        val = (val >= 0.f) ? val : alpha * val;
        y[q] = val;
        ss += val * val;
    }
    #pragma unroll
    for (int o = 16; o; o >>= 1) ss += __shfl_xor_sync(0xffffffffu, ss, o);
    float inv = 1.f / fmaxf(sqrtf(ss), L2_EPS);
    __half2 p0 = __floats2half2_rn(y[0] * inv, y[1] * inv);
    __half2 p1 = __floats2half2_rn(y[2] * inv, y[3] * inv);
    uint2 h2;
    h2.x = *reinterpret_cast<uint32_t*>(&p0);
    h2.y = *reinterpret_cast<uint32_t*>(&p1);
    *reinterpret_cast<uint2*>(&g_hF[(size_t)node * 128 + lane * 4]) = h2;
}

// ---------------- streaming store helpers ----------------------------------------
__device__ __forceinline__ void st16_cs(void* gptr, uint4 v) {
    asm volatile("st.global.cs.v4.u32 [%0], {%1, %2, %3, %4};"
                 :: "l"(gptr), "r"(v.x), "r"(v.y), "r"(v.z), "r"(v.w) : "memory");
}
__device__ __forceinline__ void st4_cs(void* gptr, uint32_t v) {
    asm volatile("st.global.cs.u32 [%0], %1;" :: "l"(gptr), "r"(v) : "memory");
}

// unpack uint4 of 8 halves into 8 named floats
#define UNPACK8(V, F)                                                     \
    {                                                                     \
        float2 _t;                                                        \
        _t = __half22float2(*reinterpret_cast<const __half2*>(&(V).x));   \
        F##0 = _t.x; F##1 = _t.y;                                         \
        _t = __half22float2(*reinterpret_cast<const __half2*>(&(V).y));   \
        F##2 = _t.x; F##3 = _t.y;                                         \
        _t = __half22float2(*reinterpret_cast<const __half2*>(&(V).z));   \
        F##4 = _t.x; F##5 = _t.y;                                         \
        _t = __half22float2(*reinterpret_cast<const __half2*>(&(V).w));   \
        F##6 = _t.x; F##7 = _t.y;                                         \
    }

#define ADD8(A, F)                                                        \
    { A[0]+=F##0; A[1]+=F##1; A[2]+=F##2; A[3]+=F##3;                     \
      A[4]+=F##4; A[5]+=F##5; A[6]+=F##6; A[7]+=F##7; }

#define DISPATCH8(ET, F)                                                  \
    { if ((ET) == 0) ADD8(a0, F) else if ((ET) == 1) ADD8(a1, F)          \
      else if ((ET) == 2) ADD8(a2, F) else ADD8(a3, F) }

// ---------------- layer-1 pre-aggregation: fp16 16B half-warp gather → fp16 g_G -
__global__ __launch_bounds__(256) void k_gather1() {
    int node = (blockIdx.x * 256 + threadIdx.x) >> 5;
    int lane = threadIdx.x & 31;
    if (node >= N_NODES) return;
    const int half = lane >> 4;       // 0 or 1
    const int hl   = lane & 15;       // lane within half-warp

    float a0[8], a1[8], a2[8], a3[8];
    #pragma unroll
    for (int j = 0; j < 8; j++) { a0[j]=0.f; a1[j]=0.f; a2[j]=0.f; a3[j]=0.f; }

    int beg = g_offs[node], end = g_offs[node + 1];

    int e = beg + half;
    for (; e + 2 < end; e += 4) {
        int p0 = g_elist[e];
        int p1 = g_elist[e + 2];
        uint4 v0 = *reinterpret_cast<const uint4*>(&g_hF[(size_t)(p0 >> 6) * 128 + hl * 8]);
        uint4 v1 = *reinterpret_cast<const uint4*>(&g_hF[(size_t)(p1 >> 6) * 128 + hl * 8]);
        float f0, f1, f2, f3, f4, f5, f6, f7;
        UNPACK8(v0, f);
        DISPATCH8(p0 & 3, f);
        UNPACK8(v1, f);
        DISPATCH8(p1 & 3, f);
    }
    for (; e < end; e += 2) {
        int p = g_elist[e];
        uint4 v = *reinterpret_cast<const uint4*>(&g_hF[(size_t)(p >> 6) * 128 + hl * 8]);
        float f0, f1, f2, f3, f4, f5, f6, f7;
        UNPACK8(v, f);
        DISPATCH8(p & 3, f);
    }

    #pragma unroll
    for (int j = 0; j < 8; j++) {
        a0[j] += __shfl_xor_sync(0xffffffffu, a0[j], 16);
        a1[j] += __shfl_xor_sync(0xffffffffu, a1[j], 16);
        a2[j] += __shfl_xor_sync(0xffffffffu, a2[j], 16);
        a3[j] += __shfl_xor_sync(0xffffffffu, a3[j], 16);
    }

    if (lane < 16) {
        size_t base = (size_t)node * GCOLS + hl * 8;
        float w0 = g_winv[node*4+0], w1 = g_winv[node*4+1];
        float w2 = g_winv[node*4+2], w3 = g_winv[node*4+3];
        {
            __half2 q0 = __floats2half2_rn(a0[0]*w0, a0[1]*w0);
            __half2 q1 = __floats2half2_rn(a0[2]*w0, a0[3]*w0);
            __half2 q2 = __floats2half2_rn(a0[4]*w0, a0[5]*w0);
            __half2 q3 = __floats2half2_rn(a0[6]*w0, a0[7]*w0);
            uint4 o; o.x=*reinterpret_cast<uint32_t*>(&q0); o.y=*reinterpret_cast<uint32_t*>(&q1);
            o.z=*reinterpret_cast<uint32_t*>(&q2); o.w=*reinterpret_cast<uint32_t*>(&q3);
            st16_cs(&g_G[base], o);
        }
        {
            __half2 q0 = __floats2half2_rn(a1[0]*w1, a1[1]*w1);
            __half2 q1 = __floats2half2_rn(a1[2]*w1, a1[3]*w1);
            __half2 q2 = __floats2half2_rn(a1[4]*w1, a1[5]*w1);
            __half2 q3 = __floats2half2_rn(a1[6]*w1, a1[7]*w1);
            uint4 o; o.x=*reinterpret_cast<uint32_t*>(&q0); o.y=*reinterpret_cast<uint32_t*>(&q1);
            o.z=*reinterpret_cast<uint32_t*>(&q2); o.w=*reinterpret_cast<uint32_t*>(&q3);
            st16_cs(&g_G[base + 128], o);
        }
        {
            __half2 q0 = __floats2half2_rn(a2[0]*w2, a2[1]*w2);
            __half2 q1 = __floats2half2_rn(a2[2]*w2, a2[3]*w2);
            __half2 q2 = __floats2half2_rn(a2[4]*w2, a2[5]*w2);
            __half2 q3 = __floats2half2_rn(a2[6]*w2, a2[7]*w2);
            uint4 o; o.x=*reinterpret_cast<uint32_t*>(&q0); o.y=*reinterpret_cast<uint32_t*>(&q1);
            o.z=*reinterpret_cast<uint32_t*>(&q2); o.w=*reinterpret_cast<uint32_t*>(&q3);
            st16_cs(&g_G[base + 256], o);
        }
        {
            __half2 q0 = __floats2half2_rn(a3[0]*w3, a3[1]*w3);
            __half2 q1 = __floats2half2_rn(a3[2]*w3, a3[3]*w3);
            __half2 q2 = __floats2half2_rn(a3[4]*w3, a3[5]*w3);
            __half2 q3 = __floats2half2_rn(a3[6]*w3, a3[7]*w3);
            uint4 o; o.x=*reinterpret_cast<uint32_t*>(&q0); o.y=*reinterpret_cast<uint32_t*>(&q1);
            o.z=*reinterpret_cast<uint32_t*>(&q2); o.w=*reinterpret_cast<uint32_t*>(&q3);
            st16_cs(&g_G[base + 384], o);
        }
    }
}

// ---------------- cp.async helper (L2-only) -------------------------------------
__device__ __forceinline__ void cp16(void* smem_dst, const void* gsrc, int src_bytes) {
    unsigned sa = (unsigned)__cvta_generic_to_shared(smem_dst);
    asm volatile("cp.async.cg.shared.global [%0], [%1], 16, %2;"
                 :: "r"(sa), "l"(gsrc), "r"(src_bytes));
}

#define AKS 40   // smem k-stride in halves (32 + 8 pad): conflict-free fragments
#define BM  256  // GEMM M tile

// ---------------- fp16 GEMM: g_hBh[N,128] = [hF|G][N,640] @ W1h^T + bias --------
// 256x128 tile (B traffic halved), 512 threads, BK=32, m16n8k16 f16 mma,
// double-buffered cp.async, fused BN stats, fp16 output.
__global__ __launch_bounds__(512, 1) void k_gemm_f16(const float* __restrict__ bias) {
    extern __shared__ char smc[];
    __half (*As)[BM][AKS]  = (__half(*)[BM][AKS])smc;                     // 2 stages
    __half (*Bs)[128][AKS] = (__half(*)[128][AKS])(smc + 2*BM*AKS*2);     // [n][k]
    float* ssum = (float*)(smc + 2*BM*AKS*2 + 2*128*AKS*2);
    float* ssq  = ssum + 128;

    const int tid  = threadIdx.x;
    const int lane = tid & 31;
    const int warp = tid >> 5;          // 0..15
    const int row0 = blockIdx.x * BM;
    const int warpM = (warp & 7) * 32;  // 8 warps along M (256)
    const int warpN = (warp >> 3) * 64; // 2 warps along N (128)
    const int lq = lane >> 2;   // 0..7
    const int lr = lane & 3;    // 0..3

    if (tid < 128) { ssum[tid] = 0.f; ssq[tid] = 0.f; }

    auto loadA = [&](int s, int kc) {
        #pragma unroll
        for (int i = 0; i < 2; i++) {
            int f = tid + i * 512;
            int r = f >> 2, c8 = (f & 3) * 8;     // 8 halves = 16 bytes
            int gr = row0 + r;
            bool valid = gr < N_NODES;
            const __half* src;
            if (kc < 128) src = &g_hF[(size_t)(valid ? gr : 0) * 128 + kc + c8];
            else          src = &g_G[(size_t)(valid ? gr : 0) * GCOLS + (kc - 128) + c8];
            cp16(&As[s][r][c8], src, valid ? 16 : 0);
        }
    };
    auto loadB = [&](int s, int kc) {
        int f = tid;                              // 512 threads cover 128x32 halves
        int r = f >> 2, c8 = (f & 3) * 8;
        cp16(&Bs[s][r][c8], &g_W1h[r * WCOLS + kc + c8], 16);
    };

    float acc[2][8][4];
    #pragma unroll
    for (int mt = 0; mt < 2; mt++)
        #pragma unroll
        for (int nt = 0; nt < 8; nt++)
            #pragma unroll
            for (int q = 0; q < 4; q++) acc[mt][nt][q] = 0.f;

    const int NT = WCOLS / 32;   // 20
    loadA(0, 0); loadB(0, 0);
    asm volatile("cp.async.commit_group;");

    for (int kt = 0; kt < NT; kt++) {
        if (kt + 1 < NT) {
            loadA((kt + 1) & 1, (kt + 1) * 32);
            loadB((kt + 1) & 1, (kt + 1) * 32);
            asm volatile("cp.async.commit_group;");
            asm volatile("cp.async.wait_group 1;");
        } else {
            asm volatile("cp.async.wait_group 0;");
        }
        __syncthreads();
        const int buf = kt & 1;

        #pragma unroll
        for (int ks = 0; ks < 2; ks++) {
            const int k0 = ks * 16;
            uint32_t bf0[8], bf1[8];
            #pragma unroll
            for (int nt = 0; nt < 8; nt++) {
                int nc = warpN + nt * 8 + lq;
                bf0[nt] = *reinterpret_cast<const uint32_t*>(&Bs[buf][nc][k0 + 2*lr]);
                bf1[nt] = *reinterpret_cast<const uint32_t*>(&Bs[buf][nc][k0 + 8 + 2*lr]);
            }
            #pragma unroll
            for (int mt = 0; mt < 2; mt++) {
                int mr = warpM + mt * 16 + lq;
                uint32_t a0 = *reinterpret_cast<const uint32_t*>(&As[buf][mr    ][k0 + 2*lr    ]);
                uint32_t a1 = *reinterpret_cast<const uint32_t*>(&As[buf][mr + 8][k0 + 2*lr    ]);
                uint32_t a2 = *reinterpret_cast<const uint32_t*>(&As[buf][mr    ][k0 + 8 + 2*lr]);
                uint32_t a3 = *reinterpret_cast<const uint32_t*>(&As[buf][mr + 8][k0 + 8 + 2*lr]);
                #pragma unroll
                for (int nt = 0; nt < 8; nt++) {
                    asm volatile(
                        "mma.sync.aligned.m16n8k16.row.col.f32.f16.f16.f32 "
                        "{%0,%1,%2,%3}, {%4,%5,%6,%7}, {%8,%9}, {%0,%1,%2,%3};"
                        : "+f"(acc[mt][nt][0]), "+f"(acc[mt][nt][1]),
                          "+f"(acc[mt][nt][2]), "+f"(acc[mt][nt][3])
                        : "r"(a0), "r"(a1), "r"(a2), "r"(a3),
                          "r"(bf0[nt]), "r"(bf1[nt]));
                }
            }
        }
        __syncthreads();
    }

    // ---- epilogue: bias + fp16 streaming store + per-column partial stats ----
    float cs[8][2], cq[8][2];
    #pragma unroll
    for (int nt = 0; nt < 8; nt++) { cs[nt][0]=0.f; cs[nt][1]=0.f; cq[nt][0]=0.f; cq[nt][1]=0.f; }

    #pragma unroll
    for (int mt = 0; mt < 2; mt++) {
        int r_lo = row0 + warpM + mt * 16 + lq;
        int r_hi = r_lo + 8;
        bool vlo = r_lo < N_NODES, vhi = r_hi < N_NODES;
        #pragma unroll
        for (int nt = 0; nt < 8; nt++) {
            int c = warpN + nt * 8 + lr * 2;
            float b0 = bias[c], b1 = bias[c + 1];
            float v0 = acc[mt][nt][0] + b0, v1 = acc[mt][nt][1] + b1;
            float v2 = acc[mt][nt][2] + b0, v3 = acc[mt][nt][3] + b1;
            if (vlo) {
                __half2 h = __floats2half2_rn(v0, v1);
                st4_cs(&g_hBh[(size_t)r_lo * 128 + c], *reinterpret_cast<uint32_t*>(&h));
                cs[nt][0] += v0; cq[nt][0] += v0 * v0;
                cs[nt][1] += v1; cq[nt][1] += v1 * v1;
            }
            if (vhi) {
                __half2 h = __floats2half2_rn(v2, v3);
                st4_cs(&g_hBh[(size_t)r_hi * 128 + c], *reinterpret_cast<uint32_t*>(&h));
                cs[nt][0] += v2; cq[nt][0] += v2 * v2;
                cs[nt][1] += v3; cq[nt][1] += v3 * v3;
            }
        }
    }
    #pragma unroll
    for (int nt = 0; nt < 8; nt++)
        #pragma unroll
        for (int p = 0; p < 2; p++) {
            #pragma unroll
            for (int off = 4; off < 32; off <<= 1) {
                cs[nt][p] += __shfl_xor_sync(0xffffffffu, cs[nt][p], off);
                cq[nt][p] += __shfl_xor_sync(0xffffffffu, cq[nt][p], off);
            }
        }
    if (lq == 0) {
        #pragma unroll
        for (int nt = 0; nt < 8; nt++)
            #pragma unroll
            for (int p = 0; p < 2; p++) {
                int c = warpN + nt * 8 + lr * 2 + p;
                atomicAdd(&ssum[c], cs[nt][p]);
                atomicAdd(&ssq[c],  cq[nt][p]);
            }
    }
    __syncthreads();
    if (tid < 128)       atomicAdd(&g_stats[256 + tid], (double)ssum[tid]);
    else if (tid < 256)  atomicAdd(&g_stats[384 + tid - 128], (double)ssq[tid - 128]);
}

// ---------------- fused BN+PReLU+L2norm+mean-pool (sorted batch, fp16 input) ----
__global__ __launch_bounds__(256) void k_bnpool(const int* __restrict__ batch,
                                                const float* __restrict__ gamma,
                                                const float* __restrict__ beta,
                                                const float* __restrict__ pa) {
    const int NPW = 16;
    int warpg = (blockIdx.x * 256 + threadIdx.x) >> 5;
    int lane  = threadIdx.x & 31;
    int n0 = warpg * NPW;
    if (n0 >= N_NODES) return;
    int n1 = min(n0 + NPW, N_NODES);
    float alpha = pa[1];

    float mu[4], sc[4], bt[4];
    #pragma unroll
    for (int q = 0; q < 4; q++) {
        int c = lane * 4 + q;
        double m  = g_stats[256 + c] * (1.0 / N_NODES);
        double vv = g_stats[384 + c] * (1.0 / N_NODES) - m * m;
        mu[q] = (float)m;
        sc[q] = rsqrtf((float)vv + BN_EPS) * gamma[c];
        bt[q] = beta[c];
    }

    float acc[4] = {0.f, 0.f, 0.f, 0.f};
    int cur = -1, cnt = 0;
    for (int n = n0; n < n1; n++) {
        uint2 raw = __ldcs(reinterpret_cast<const uint2*>(&g_hBh[(size_t)n * 128 + lane * 4]));
        float2 f01 = __half22float2(*reinterpret_cast<const __half2*>(&raw.x));
        float2 f23 = __half22float2(*reinterpret_cast<const __half2*>(&raw.y));
        float y[4] = { f01.x, f01.y, f23.x, f23.y };
        float ss = 0.f;
        #pragma unroll
        for (int q = 0; q < 4; q++) {
            float val = (y[q] - mu[q]) * sc[q] + bt[q];
            val = (val >= 0.f) ? val : alpha * val;
            y[q] = val;
            ss += val * val;
        }
        #pragma unroll
        for (int o = 16; o; o >>= 1) ss += __shfl_xor_sync(0xffffffffu, ss, o);
        float inv = 1.f / fmaxf(sqrtf(ss), L2_EPS);
        int g = batch[n];
        if (g != cur) {
            if (cur >= 0) {
                #pragma unroll
                for (int q = 0; q < 4; q++) atomicAdd(&g_pool[cur * 128 + lane * 4 + q], acc[q]);
                if (lane == 0) atomicAdd(&g_gcnt[cur], cnt);
            }
            cur = g; cnt = 1;
            #pragma unroll
            for (int q = 0; q < 4; q++) acc[q] = y[q] * inv;
        } else {
            cnt++;
            #pragma unroll
            for (int q = 0; q < 4; q++) acc[q] += y[q] * inv;
        }
    }
    if (cur >= 0) {
        #pragma unroll
        for (int q = 0; q < 4; q++) atomicAdd(&g_pool[cur * 128 + lane * 4 + q], acc[q]);
        if (lane == 0) atomicAdd(&g_gcnt[cur], cnt);
    }
}

// ---------------- MLP head: one block per graph ---------------------------------
__global__ __launch_bounds__(256) void k_mlp(const float* __restrict__ fc1w, const float* __restrict__ fc1b,
                                             const float* __restrict__ fc2w, const float* __restrict__ fc2b,
                                             const float* __restrict__ ow,  const float* __restrict__ ob,
                                             float* __restrict__ out) {
    int g = blockIdx.x;
    int t = threadIdx.x;
    __shared__ float sg[128], s1[256], s2[128], red[256];
    float invc = 1.f / fmaxf((float)g_gcnt[g], 1.f);
    if (t < 128) sg[t] = g_pool[g * 128 + t] * invc;
    __syncthreads();
    float s = fc1b[t];
    #pragma unroll 8
    for (int k = 0; k < 128; k++) s += sg[k] * fc1w[k * 256 + t];
    s1[t] = fmaxf(s, 0.f);
    __syncthreads();
    if (t < 128) {
        float s2v = fc2b[t];
        #pragma unroll 8
        for (int k = 0; k < 256; k++) s2v += s1[k] * fc2w[k * 128 + t];
        s2[t] = fmaxf(s2v, 0.f);
    }
    __syncthreads();
    red[t] = (t < 128) ? s2[t] * ow[t] : 0.f;
    __syncthreads();
    for (int o = 128; o > 0; o >>= 1) {
        if (t < o) red[t] += red[t + o];
        __syncthreads();
    }
    if (t == 0) out[g] = red[0] + ob[0];
}

// =============================================================================
extern "C" void kernel_launch(void* const* d_in, const int* in_sizes, int n_in,
                              void* d_out, int out_size) {
    const float* x      = (const float*)d_in[0];
    const int*   ei     = (const int*)  d_in[1];
    const int*   etype  = (const int*)  d_in[2];
    const int*   batch  = (const int*)  d_in[3];
    const float* emb    = (const float*)d_in[4];
    const float* Wrel   = (const float*)d_in[5];
    const float* Wroot  = (const float*)d_in[6];
    const float* cbias  = (const float*)d_in[7];
    const float* gamma  = (const float*)d_in[8];
    const float* beta   = (const float*)d_in[9];
    const float* pa     = (const float*)d_in[10];
    const float* fc1w   = (const float*)d_in[11];
    const float* fc1b   = (const float*)d_in[12];
    const float* fc2w   = (const float*)d_in[13];
    const float* fc2b   = (const float*)d_in[14];
    const float* ow     = (const float*)d_in[15];
    const float* ob     = (const float*)d_in[16];
    float* out = (float*)d_out;

    const int TB = 256;
    const int GEMM_SMEM = 2*BM*AKS*2 + 2*128*AKS*2 + 256*4;   // A+B stages (fp16) + stats

    static cudaStream_t s1 = nullptr;
    static cudaEvent_t evStart, evW;
    if (!s1) {
        cudaFuncSetAttribute(k_gemm_f16, cudaFuncAttributeMaxDynamicSharedMemorySize, GEMM_SMEM);
        cudaStreamCreateWithFlags(&s1, cudaStreamNonBlocking);
        cudaEventCreateWithFlags(&evStart, cudaEventDisableTiming);
        cudaEventCreateWithFlags(&evW, cudaEventDisableTiming);
    }

    // ---- fork: weights on s1 (independent of graph structure) ----
    cudaEventRecord(evStart, 0);
    cudaStreamWaitEvent(s1, evStart, 0);
    k_weights<<<(N_TYPES * WCOLS + WCOLS * 128 + TB - 1) / TB, TB, 0, s1>>>(emb, Wrel, Wroot, cbias);
    cudaEventRecord(evW, s1);

    // ---- prep + graph structure (default stream) ----
    k_prep<<<(N_NODES * 4 + TB - 1) / TB, TB>>>(x);
    k_count<<<(N_EDGES + TB - 1) / TB, TB>>>(ei, etype);
    k_scan1<<<NB_SCAN, 256>>>();
    k_scan2<<<1, 512>>>();
    k_scan3<<<(N_NODES + TB - 1) / TB, TB>>>();
    k_fill<<<(N_EDGES + TB - 1) / TB, TB>>>(ei, etype);

    // join weights before layer 0 (agg0 needs g_T0)
    cudaStreamWaitEvent(0, evW, 0);

    const int nodeWarpBlocks = (N_NODES * 32 + TB - 1) / TB;
    const int npwBlocks = ((N_NODES + 15) / 16 * 32 + TB - 1) / TB;

    // ---- layer 0 (table shortcut; f32 stats source, fp16 mirror out) ----
    k_agg0<<<nodeWarpBlocks, TB>>>();
    k_bnstats0<<<512, 128>>>();
    k_bnapply0<<<nodeWarpBlocks, TB>>>(gamma, beta, pa);

    // ---- layer 1: fp16 half-warp gather → fp16 G, then fp16 GEMM (fused stats) --
    k_gather1<<<nodeWarpBlocks, TB>>>();
    k_gemm_f16<<<(N_NODES + BM - 1) / BM, 512, GEMM_SMEM>>>(cbias + 128);

    // ---- fused BN+PReLU+L2norm+pool, then MLP ----
    k_bnpool<<<npwBlocks, TB>>>(batch, gamma + 128, beta + 128, pa);
    k_mlp<<<N_GRAPHS, 256>>>(fc1w, fc1b, fc2w, fc2b, ow, ob, out);
}

// round 17
// speedup vs baseline: 1.0213x; 1.0213x over previous
#include <cuda_runtime.h>
#include <cuda_fp16.h>
#include <cstdint>

#define N_NODES 100000
#define N_EDGES 1600000
#define N_GRAPHS 512
#define N_REL 4
#define N_TYPES 13
#define HID 128
#define WCOLS 640            // logical K: [self(128) | rel0..3 (4*128)]
#define GCOLS 512            // stored aggregate cols (self removed)
#define BN_EPS 1e-5f
#define L2_EPS 1e-12f
#define NB_SCAN ((N_NODES + 255) / 256)   // 391

// ---------------- device scratch ---------------------------------------------
__device__ __align__(16) float  g_hA[N_NODES * HID];           // layer-0 pre-BN (fp32)
__device__ __align__(16) __half g_hF[N_NODES * HID];           // layer-0 post-BN (fp16)
__device__ __align__(16) __half g_hBh[N_NODES * HID];          // layer-1 GEMM out (fp16)
__device__ __align__(16) __half g_G[(size_t)N_NODES * GCOLS];  // per-rel aggregates (fp16)
__device__ __align__(16) float  g_T0[N_TYPES * WCOLS];
__device__ __align__(16) __half g_W1h[128 * WCOLS];            // packed weights, [n][k] fp16
__device__ int    g_ntype[N_NODES];
__device__ int    g_cnt4[N_NODES * 4];
__device__ float  g_winv[N_NODES * 4];
__device__ int    g_offs[N_NODES + 1];
__device__ int    g_cursor[N_NODES];
__device__ int    g_bsum[NB_SCAN];
__device__ int    g_bpre[NB_SCAN];
__device__ int    g_elist[N_EDGES];                            // packed (src<<6)|(ts<<2)|et
__device__ double g_stats[512];   // [0:128) sum0 [128:256) sq0 [256:384) sum1 [384:512) sq1
__device__ __align__(16) float g_pool[N_GRAPHS * HID];
__device__ int    g_gcnt[N_GRAPHS];

// ---------------- prep: zero accumulators + node types ------------------------
__global__ void k_prep(const float* __restrict__ x) {
    int i = blockIdx.x * blockDim.x + threadIdx.x;
    if (i < N_NODES * 4) g_cnt4[i] = 0;
    if (i < 512) g_stats[i] = 0.0;
    if (i < N_GRAPHS * HID) g_pool[i] = 0.f;
    if (i < N_GRAPHS) g_gcnt[i] = 0;
    if (i < N_NODES) {
        const float* row = x + (size_t)i * N_TYPES;
        int t = 0; float best = row[0];
        #pragma unroll
        for (int q = 1; q < N_TYPES; q++) {
            float v = row[q];
            if (v > best) { best = v; t = q; }
        }
        g_ntype[i] = t;
    }
}

// ---------------- per-(dst,rel) in-degree counts ------------------------------
__global__ void k_count(const int* __restrict__ ei, const int* __restrict__ etype) {
    int e = blockIdx.x * blockDim.x + threadIdx.x;
    if (e >= N_EDGES) return;
    int dst = ei[N_EDGES + e];
    int et  = etype[e];
    atomicAdd(&g_cnt4[dst * 4 + et], 1);
}

// ---------------- parallel scan, phase 1: block-local (+ winv) ----------------
__global__ void k_scan1() {
    __shared__ int sh[256];
    int tid = threadIdx.x;
    int i = blockIdx.x * 256 + tid;
    int d = 0;
    if (i < N_NODES) {
        int c0 = g_cnt4[4*i+0], c1 = g_cnt4[4*i+1];
        int c2 = g_cnt4[4*i+2], c3 = g_cnt4[4*i+3];
        d = c0 + c1 + c2 + c3;
        g_winv[4*i+0] = 1.f / fmaxf((float)c0, 1.f);
        g_winv[4*i+1] = 1.f / fmaxf((float)c1, 1.f);
        g_winv[4*i+2] = 1.f / fmaxf((float)c2, 1.f);
        g_winv[4*i+3] = 1.f / fmaxf((float)c3, 1.f);
    }
    sh[tid] = d;
    __syncthreads();
    #pragma unroll
    for (int off = 1; off < 256; off <<= 1) {
        int t = (tid >= off) ? sh[tid - off] : 0;
        __syncthreads();
        sh[tid] += t;
        __syncthreads();
    }
    if (i < N_NODES) g_offs[i] = sh[tid] - d;          // block-local exclusive
    if (tid == 255) g_bsum[blockIdx.x] = sh[255];
}

// ---------------- phase 2: scan block sums (1 block) ---------------------------
__global__ void k_scan2() {
    __shared__ int sh[512];
    int tid = threadIdx.x;
    int v = (tid < NB_SCAN) ? g_bsum[tid] : 0;
    sh[tid] = v;
    __syncthreads();
    #pragma unroll
    for (int off = 1; off < 512; off <<= 1) {
        int t = (tid >= off) ? sh[tid - off] : 0;
        __syncthreads();
        sh[tid] += t;
        __syncthreads();
    }
    if (tid < NB_SCAN) g_bpre[tid] = sh[tid] - v;      // exclusive
}

// ---------------- phase 3: add base, emit cursor -------------------------------
__global__ void k_scan3() {
    int i = blockIdx.x * blockDim.x + threadIdx.x;
    if (i < N_NODES) {
        int o = g_offs[i] + g_bpre[i >> 8];
        g_offs[i] = o;
        g_cursor[i] = o;
    }
    if (i == 0) g_offs[N_NODES] = N_EDGES;
}

// ---------------- fill CSR edge list (packs src type) ---------------------------
__global__ void k_fill(const int* __restrict__ ei, const int* __restrict__ etype) {
    int e = blockIdx.x * blockDim.x + threadIdx.x;
    if (e >= N_EDGES) return;
    int src = ei[e];
    int dst = ei[N_EDGES + e];
    int et  = etype[e];
    int ts  = g_ntype[src];
    int pos = atomicAdd(&g_cursor[dst], 1);
    g_elist[pos] = (src << 6) | (ts << 2) | et;
}

// ---------------- weights: layer-0 table + transposed fp16 layer-1 weights ------
__global__ void k_weights(const float* __restrict__ emb, const float* __restrict__ Wrel,
                          const float* __restrict__ Wroot, const float* __restrict__ bias) {
    int i = blockIdx.x * blockDim.x + threadIdx.x;
    if (i < N_TYPES * WCOLS) {
        int t = i / WCOLS, c = i % WCOLS;
        float s;
        if (c < 128) {
            s = bias[c];
            #pragma unroll 8
            for (int k = 0; k < 128; k++) s += emb[t*128 + k] * Wroot[k*128 + c];
        } else {
            int r = (c - 128) >> 7, j = (c - 128) & 127;
            const float* wr = Wrel + r * 16384;
            s = 0.f;
            #pragma unroll 8
            for (int k = 0; k < 128; k++) s += emb[t*128 + k] * wr[k*128 + j];
        }
        g_T0[i] = s;
    }
    int w = i - N_TYPES * WCOLS;
    if (w >= 0 && w < WCOLS * 128) {
        int kk = w / 128, c = w % 128;
        float v;
        if (kk < 128) v = Wroot[16384 + kk*128 + c];
        else {
            int r = (kk - 128) >> 7, k = (kk - 128) & 127;
            v = Wrel[(4 + r) * 16384 + k*128 + c];
        }
        g_W1h[c * WCOLS + kk] = __float2half_rn(v);   // transposed [n][k]
    }
}

// ---------------- layer-0 aggregation: elist stream + L1 table → g_hA (f32) -----
__global__ __launch_bounds__(256) void k_agg0() {
    int node = (blockIdx.x * 256 + threadIdx.x) >> 5;
    int lane = threadIdx.x & 31;
    if (node >= N_NODES) return;
    float w0 = g_winv[node*4+0], w1 = g_winv[node*4+1];
    float w2 = g_winv[node*4+2], w3 = g_winv[node*4+3];
    float4 acc = *reinterpret_cast<const float4*>(&g_T0[g_ntype[node] * WCOLS + lane * 4]);
    int beg = g_offs[node], end = g_offs[node + 1];

    auto addw = [&](int et, float4 m) {
        float w = (et == 0) ? w0 : (et == 1) ? w1 : (et == 2) ? w2 : w3;
        acc.x += m.x * w; acc.y += m.y * w; acc.z += m.z * w; acc.w += m.w * w;
    };
    auto t0row = [&](int p) -> const float4* {
        int ts = (p >> 2) & 15, et = p & 3;
        return reinterpret_cast<const float4*>(&g_T0[ts * WCOLS + 128 + et * 128 + lane * 4]);
    };

    int e = beg;
    for (; e + 4 <= end; e += 4) {
        int p0 = g_elist[e], p1 = g_elist[e+1], p2 = g_elist[e+2], p3 = g_elist[e+3];
        float4 m0 = *t0row(p0);
        float4 m1 = *t0row(p1);
        float4 m2 = *t0row(p2);
        float4 m3 = *t0row(p3);
        addw(p0 & 3, m0); addw(p1 & 3, m1); addw(p2 & 3, m2); addw(p3 & 3, m3);
    }
    for (; e < end; e++) {
        int p = g_elist[e];
        float4 m = *t0row(p);
        addw(p & 3, m);
    }
    *reinterpret_cast<float4*>(&g_hA[(size_t)node * 128 + lane * 4]) = acc;
}

// ---------------- BN stats layer 0 (separate pass: 512 atomics/address) ---------
__global__ void k_bnstats0() {
    int col = threadIdx.x;             // 128 threads
    double s = 0.0, s2 = 0.0;
    for (int r = blockIdx.x; r < N_NODES; r += gridDim.x) {
        float v = g_hA[(size_t)r * 128 + col];
        s  += (double)v;
        s2 += (double)v * (double)v;
    }
    atomicAdd(&g_stats[col], s);
    atomicAdd(&g_stats[128 + col], s2);
}

// ---------------- BN apply + PReLU + L2norm: g_hA (f32) → g_hF (fp16) only ------
__global__ __launch_bounds__(256) void k_bnapply0(const float* __restrict__ gamma,
                                                  const float* __restrict__ beta,
                                                  const float* __restrict__ pa) {
    int node = (blockIdx.x * 256 + threadIdx.x) >> 5;
    int lane = threadIdx.x & 31;
    if (node >= N_NODES) return;
    float alpha = pa[0];
    float4 v = *reinterpret_cast<const float4*>(&g_hA[(size_t)node * 128 + lane * 4]);
    float vin[4] = { v.x, v.y, v.z, v.w };
    float y[4]; float ss = 0.f;
    #pragma unroll
    for (int q = 0; q < 4; q++) {
        int c = lane * 4 + q;
        double mu  = g_stats[c] * (1.0 / N_NODES);
        double var = g_stats[128 + c] * (1.0 / N_NODES) - mu * mu;
        float sc = rsqrtf((float)var + BN_EPS) * gamma[c];
        float val = (vin[q] - (float)mu) * sc + beta[c];
        val = (val >= 0.f) ? val : alpha * val;
        y[q] = val;
        ss += val * val;
    }
    #pragma unroll
    for (int o = 16; o; o >>= 1) ss += __shfl_xor_sync(0xffffffffu, ss, o);
    float inv = 1.f / fmaxf(sqrtf(ss), L2_EPS);
    __half2 p0 = __floats2half2_rn(y[0] * inv, y[1] * inv);
    __half2 p1 = __floats2half2_rn(y[2] * inv, y[3] * inv);
    uint2 h2;
    h2.x = *reinterpret_cast<uint32_t*>(&p0);
    h2.y = *reinterpret_cast<uint32_t*>(&p1);
    *reinterpret_cast<uint2*>(&g_hF[(size_t)node * 128 + lane * 4]) = h2;
}

// ---------------- streaming store helpers ----------------------------------------
__device__ __forceinline__ void st16_cs(void* gptr, uint4 v) {
    asm volatile("st.global.cs.v4.u32 [%0], {%1, %2, %3, %4};"
                 :: "l"(gptr), "r"(v.x), "r"(v.y), "r"(v.z), "r"(v.w) : "memory");
}
__device__ __forceinline__ void st4_cs(void* gptr, uint32_t v) {
    asm volatile("st.global.cs.u32 [%0], %1;" :: "l"(gptr), "r"(v) : "memory");
}

// unpack uint4 of 8 halves into 8 named floats
#define UNPACK8(V, F)                                                     \
    {                                                                     \
        float2 _t;                                                        \
        _t = __half22float2(*reinterpret_cast<const __half2*>(&(V).x));   \
        F##0 = _t.x; F##1 = _t.y;                                         \
        _t = __half22float2(*reinterpret_cast<const __half2*>(&(V).y));   \
        F##2 = _t.x; F##3 = _t.y;                                         \
        _t = __half22float2(*reinterpret_cast<const __half2*>(&(V).z));   \
        F##4 = _t.x; F##5 = _t.y;                                         \
        _t = __half22float2(*reinterpret_cast<const __half2*>(&(V).w));   \
        F##6 = _t.x; F##7 = _t.y;                                         \
    }

#define ADD8(A, F)                                                        \
    { A[0]+=F##0; A[1]+=F##1; A[2]+=F##2; A[3]+=F##3;                     \
      A[4]+=F##4; A[5]+=F##5; A[6]+=F##6; A[7]+=F##7; }

#define DISPATCH8(ET, F)                                                  \
    { if ((ET) == 0) ADD8(a0, F) else if ((ET) == 1) ADD8(a1, F)          \
      else if ((ET) == 2) ADD8(a2, F) else ADD8(a3, F) }

// ---------------- layer-1 pre-aggregation: fp16 16B half-warp gather → fp16 g_G -
// One warp per node. Half-warp h handles edges beg+h, beg+h+2, ... Each lane
// loads 16B (8 halves) of the 256B fp16 row. x4 unroll per half-warp:
// 8 independent row loads in flight per warp.
__global__ __launch_bounds__(256) void k_gather1() {
    int node = (blockIdx.x * 256 + threadIdx.x) >> 5;
    int lane = threadIdx.x & 31;
    if (node >= N_NODES) return;
    const int half = lane >> 4;       // 0 or 1
    const int hl   = lane & 15;       // lane within half-warp

    float a0[8], a1[8], a2[8], a3[8];
    #pragma unroll
    for (int j = 0; j < 8; j++) { a0[j]=0.f; a1[j]=0.f; a2[j]=0.f; a3[j]=0.f; }

    int beg = g_offs[node], end = g_offs[node + 1];

    int e = beg + half;
    // x4 unroll per half-warp (stride 2 within half): 8 edges in flight per warp
    for (; e + 6 < end; e += 8) {
        int p0 = g_elist[e];
        int p1 = g_elist[e + 2];
        int p2 = g_elist[e + 4];
        int p3 = g_elist[e + 6];
        uint4 v0 = *reinterpret_cast<const uint4*>(&g_hF[(size_t)(p0 >> 6) * 128 + hl * 8]);
        uint4 v1 = *reinterpret_cast<const uint4*>(&g_hF[(size_t)(p1 >> 6) * 128 + hl * 8]);
        uint4 v2 = *reinterpret_cast<const uint4*>(&g_hF[(size_t)(p2 >> 6) * 128 + hl * 8]);
        uint4 v3 = *reinterpret_cast<const uint4*>(&g_hF[(size_t)(p3 >> 6) * 128 + hl * 8]);
        float f0, f1, f2, f3, f4, f5, f6, f7;
        UNPACK8(v0, f);
        DISPATCH8(p0 & 3, f);
        UNPACK8(v1, f);
        DISPATCH8(p1 & 3, f);
        UNPACK8(v2, f);
        DISPATCH8(p2 & 3, f);
        UNPACK8(v3, f);
        DISPATCH8(p3 & 3, f);
    }
    for (; e < end; e += 2) {
        int p = g_elist[e];
        uint4 v = *reinterpret_cast<const uint4*>(&g_hF[(size_t)(p >> 6) * 128 + hl * 8]);
        float f0, f1, f2, f3, f4, f5, f6, f7;
        UNPACK8(v, f);
        DISPATCH8(p & 3, f);
    }

    #pragma unroll
    for (int j = 0; j < 8; j++) {
        a0[j] += __shfl_xor_sync(0xffffffffu, a0[j], 16);
        a1[j] += __shfl_xor_sync(0xffffffffu, a1[j], 16);
        a2[j] += __shfl_xor_sync(0xffffffffu, a2[j], 16);
        a3[j] += __shfl_xor_sync(0xffffffffu, a3[j], 16);
    }

    if (lane < 16) {
        size_t base = (size_t)node * GCOLS + hl * 8;
        float w0 = g_winv[node*4+0], w1 = g_winv[node*4+1];
        float w2 = g_winv[node*4+2], w3 = g_winv[node*4+3];
        {
            __half2 q0 = __floats2half2_rn(a0[0]*w0, a0[1]*w0);
            __half2 q1 = __floats2half2_rn(a0[2]*w0, a0[3]*w0);
            __half2 q2 = __floats2half2_rn(a0[4]*w0, a0[5]*w0);
            __half2 q3 = __floats2half2_rn(a0[6]*w0, a0[7]*w0);
            uint4 o; o.x=*reinterpret_cast<uint32_t*>(&q0); o.y=*reinterpret_cast<uint32_t*>(&q1);
            o.z=*reinterpret_cast<uint32_t*>(&q2); o.w=*reinterpret_cast<uint32_t*>(&q3);
            st16_cs(&g_G[base], o);
        }
        {
            __half2 q0 = __floats2half2_rn(a1[0]*w1, a1[1]*w1);
            __half2 q1 = __floats2half2_rn(a1[2]*w1, a1[3]*w1);
            __half2 q2 = __floats2half2_rn(a1[4]*w1, a1[5]*w1);
            __half2 q3 = __floats2half2_rn(a1[6]*w1, a1[7]*w1);
            uint4 o; o.x=*reinterpret_cast<uint32_t*>(&q0); o.y=*reinterpret_cast<uint32_t*>(&q1);
            o.z=*reinterpret_cast<uint32_t*>(&q2); o.w=*reinterpret_cast<uint32_t*>(&q3);
            st16_cs(&g_G[base + 128], o);
        }
        {
            __half2 q0 = __floats2half2_rn(a2[0]*w2, a2[1]*w2);
            __half2 q1 = __floats2half2_rn(a2[2]*w2, a2[3]*w2);
            __half2 q2 = __floats2half2_rn(a2[4]*w2, a2[5]*w2);
            __half2 q3 = __floats2half2_rn(a2[6]*w2, a2[7]*w2);
            uint4 o; o.x=*reinterpret_cast<uint32_t*>(&q0); o.y=*reinterpret_cast<uint32_t*>(&q1);
            o.z=*reinterpret_cast<uint32_t*>(&q2); o.w=*reinterpret_cast<uint32_t*>(&q3);
            st16_cs(&g_G[base + 256], o);
        }
        {
            __half2 q0 = __floats2half2_rn(a3[0]*w3, a3[1]*w3);
            __half2 q1 = __floats2half2_rn(a3[2]*w3, a3[3]*w3);
            __half2 q2 = __floats2half2_rn(a3[4]*w3, a3[5]*w3);
            __half2 q3 = __floats2half2_rn(a3[6]*w3, a3[7]*w3);
            uint4 o; o.x=*reinterpret_cast<uint32_t*>(&q0); o.y=*reinterpret_cast<uint32_t*>(&q1);
            o.z=*reinterpret_cast<uint32_t*>(&q2); o.w=*reinterpret_cast<uint32_t*>(&q3);
            st16_cs(&g_G[base + 384], o);
        }
    }
}

// ---------------- cp.async helper (L2-only) -------------------------------------
__device__ __forceinline__ void cp16(void* smem_dst, const void* gsrc, int src_bytes) {
    unsigned sa = (unsigned)__cvta_generic_to_shared(smem_dst);
    asm volatile("cp.async.cg.shared.global [%0], [%1], 16, %2;"
                 :: "r"(sa), "l"(gsrc), "r"(src_bytes));
}

#define AKS 40   // smem k-stride in halves (32 + 8 pad): conflict-free fragments

// ---------------- fp16 GEMM: g_hBh[N,128] = [hF|G][N,640] @ W1h^T + bias --------
// 128x128 tile, BK=32, m16n8k16 f16 mma (f32 accum), double-buffered cp.async,
// fused BN stats (layer 1), fp16 output.
__global__ __launch_bounds__(256, 2) void k_gemm_f16(const float* __restrict__ bias) {
    extern __shared__ char smc[];
    __half (*As)[128][AKS] = (__half(*)[128][AKS])smc;                    // 2 stages
    __half (*Bs)[128][AKS] = (__half(*)[128][AKS])(smc + 2*128*AKS*2);    // [n][k]
    float* ssum = (float*)(smc + 4*128*AKS*2);
    float* ssq  = ssum + 128;

    const int tid  = threadIdx.x;
    const int lane = tid & 31;
    const int warp = tid >> 5;
    const int row0 = blockIdx.x * 128;
    const int warpM = (warp & 3) * 32;
    const int warpN = (warp >> 2) * 64;
    const int lq = lane >> 2;   // 0..7
    const int lr = lane & 3;    // 0..3

    if (tid < 128) { ssum[tid] = 0.f; ssq[tid] = 0.f; }

    auto loadA = [&](int s, int kc) {
        #pragma unroll
        for (int i = 0; i < 2; i++) {
            int f = tid + i * 256;
            int r = f >> 2, c8 = (f & 3) * 8;     // 8 halves = 16 bytes
            int gr = row0 + r;
            bool valid = gr < N_NODES;
            const __half* src;
            if (kc < 128) src = &g_hF[(size_t)(valid ? gr : 0) * 128 + kc + c8];
            else          src = &g_G[(size_t)(valid ? gr : 0) * GCOLS + (kc - 128) + c8];
            cp16(&As[s][r][c8], src, valid ? 16 : 0);
        }
    };
    auto loadB = [&](int s, int kc) {
        #pragma unroll
        for (int i = 0; i < 2; i++) {
            int f = tid + i * 256;
            int r = f >> 2, c8 = (f & 3) * 8;
            cp16(&Bs[s][r][c8], &g_W1h[r * WCOLS + kc + c8], 16);
        }
    };

    float acc[2][8][4];
    #pragma unroll
    for (int mt = 0; mt < 2; mt++)
        #pragma unroll
        for (int nt = 0; nt < 8; nt++)
            #pragma unroll
            for (int q = 0; q < 4; q++) acc[mt][nt][q] = 0.f;

    const int NT = WCOLS / 32;   // 20
    loadA(0, 0); loadB(0, 0);
    asm volatile("cp.async.commit_group;");

    for (int kt = 0; kt < NT; kt++) {
        if (kt + 1 < NT) {
            loadA((kt + 1) & 1, (kt + 1) * 32);
            loadB((kt + 1) & 1, (kt + 1) * 32);
            asm volatile("cp.async.commit_group;");
            asm volatile("cp.async.wait_group 1;");
        } else {
            asm volatile("cp.async.wait_group 0;");
        }
        __syncthreads();
        const int buf = kt & 1;

        #pragma unroll
        for (int ks = 0; ks < 2; ks++) {
            const int k0 = ks * 16;
            uint32_t bf0[8], bf1[8];
            #pragma unroll
            for (int nt = 0; nt < 8; nt++) {
                int nc = warpN + nt * 8 + lq;
                bf0[nt] = *reinterpret_cast<const uint32_t*>(&Bs[buf][nc][k0 + 2*lr]);
                bf1[nt] = *reinterpret_cast<const uint32_t*>(&Bs[buf][nc][k0 + 8 + 2*lr]);
            }
            #pragma unroll
            for (int mt = 0; mt < 2; mt++) {
                int mr = warpM + mt * 16 + lq;
                uint32_t a0 = *reinterpret_cast<const uint32_t*>(&As[buf][mr    ][k0 + 2*lr    ]);
                uint32_t a1 = *reinterpret_cast<const uint32_t*>(&As[buf][mr + 8][k0 + 2*lr    ]);
                uint32_t a2 = *reinterpret_cast<const uint32_t*>(&As[buf][mr    ][k0 + 8 + 2*lr]);
                uint32_t a3 = *reinterpret_cast<const uint32_t*>(&As[buf][mr + 8][k0 + 8 + 2*lr]);
                #pragma unroll
                for (int nt = 0; nt < 8; nt++) {
                    asm volatile(
                        "mma.sync.aligned.m16n8k16.row.col.f32.f16.f16.f32 "
                        "{%0,%1,%2,%3}, {%4,%5,%6,%7}, {%8,%9}, {%0,%1,%2,%3};"
                        : "+f"(acc[mt][nt][0]), "+f"(acc[mt][nt][1]),
                          "+f"(acc[mt][nt][2]), "+f"(acc[mt][nt][3])
                        : "r"(a0), "r"(a1), "r"(a2), "r"(a3),
                          "r"(bf0[nt]), "r"(bf1[nt]));
                }
            }
        }
        __syncthreads();
    }

    // ---- epilogue: bias + fp16 streaming store + per-column partial stats ----
    float cs[8][2], cq[8][2];
    #pragma unroll
    for (int nt = 0; nt < 8; nt++) { cs[nt][0]=0.f; cs[nt][1]=0.f; cq[nt][0]=0.f; cq[nt][1]=0.f; }

    #pragma unroll
    for (int mt = 0; mt < 2; mt++) {
        int r_lo = row0 + warpM + mt * 16 + lq;
        int r_hi = r_lo + 8;
        bool vlo = r_lo < N_NODES, vhi = r_hi < N_NODES;
        #pragma unroll
        for (int nt = 0; nt < 8; nt++) {
            int c = warpN + nt * 8 + lr * 2;
            float b0 = bias[c], b1 = bias[c + 1];
            float v0 = acc[mt][nt][0] + b0, v1 = acc[mt][nt][1] + b1;
            float v2 = acc[mt][nt][2] + b0, v3 = acc[mt][nt][3] + b1;
            if (vlo) {
                __half2 h = __floats2half2_rn(v0, v1);
                st4_cs(&g_hBh[(size_t)r_lo * 128 + c], *reinterpret_cast<uint32_t*>(&h));
                cs[nt][0] += v0; cq[nt][0] += v0 * v0;
                cs[nt][1] += v1; cq[nt][1] += v1 * v1;
            }
            if (vhi) {
                __half2 h = __floats2half2_rn(v2, v3);
                st4_cs(&g_hBh[(size_t)r_hi * 128 + c], *reinterpret_cast<uint32_t*>(&h));
                cs[nt][0] += v2; cq[nt][0] += v2 * v2;
                cs[nt][1] += v3; cq[nt][1] += v3 * v3;
            }
        }
    }
    #pragma unroll
    for (int nt = 0; nt < 8; nt++)
        #pragma unroll
        for (int p = 0; p < 2; p++) {
            #pragma unroll
            for (int off = 4; off < 32; off <<= 1) {
                cs[nt][p] += __shfl_xor_sync(0xffffffffu, cs[nt][p], off);
                cq[nt][p] += __shfl_xor_sync(0xffffffffu, cq[nt][p], off);
            }
        }
    if (lq == 0) {
        #pragma unroll
        for (int nt = 0; nt < 8; nt++)
            #pragma unroll
            for (int p = 0; p < 2; p++) {
                int c = warpN + nt * 8 + lr * 2 + p;
                atomicAdd(&ssum[c], cs[nt][p]);
                atomicAdd(&ssq[c],  cq[nt][p]);
            }
    }
    __syncthreads();
    if (tid < 128)       atomicAdd(&g_stats[256 + tid], (double)ssum[tid]);
    else                 atomicAdd(&g_stats[384 + tid - 128], (double)ssq[tid - 128]);
}

// ---------------- fused BN+PReLU+L2norm+mean-pool (sorted batch, fp16 input) ----
__global__ __launch_bounds__(256) void k_bnpool(const int* __restrict__ batch,
                                                const float* __restrict__ gamma,
                                                const float* __restrict__ beta,
                                                const float* __restrict__ pa) {
    const int NPW = 16;
    int warpg = (blockIdx.x * 256 + threadIdx.x) >> 5;
    int lane  = threadIdx.x & 31;
    int n0 = warpg * NPW;
    if (n0 >= N_NODES) return;
    int n1 = min(n0 + NPW, N_NODES);
    float alpha = pa[1];

    float mu[4], sc[4], bt[4];
    #pragma unroll
    for (int q = 0; q < 4; q++) {
        int c = lane * 4 + q;
        double m  = g_stats[256 + c] * (1.0 / N_NODES);
        double vv = g_stats[384 + c] * (1.0 / N_NODES) - m * m;
        mu[q] = (float)m;
        sc[q] = rsqrtf((float)vv + BN_EPS) * gamma[c];
        bt[q] = beta[c];
    }

    float acc[4] = {0.f, 0.f, 0.f, 0.f};
    int cur = -1, cnt = 0;
    for (int n = n0; n < n1; n++) {
        uint2 raw = __ldcs(reinterpret_cast<const uint2*>(&g_hBh[(size_t)n * 128 + lane * 4]));
        float2 f01 = __half22float2(*reinterpret_cast<const __half2*>(&raw.x));
        float2 f23 = __half22float2(*reinterpret_cast<const __half2*>(&raw.y));
        float y[4] = { f01.x, f01.y, f23.x, f23.y };
        float ss = 0.f;
        #pragma unroll
        for (int q = 0; q < 4; q++) {
            float val = (y[q] - mu[q]) * sc[q] + bt[q];
            val = (val >= 0.f) ? val : alpha * val;
            y[q] = val;
            ss += val * val;
        }
        #pragma unroll
        for (int o = 16; o; o >>= 1) ss += __shfl_xor_sync(0xffffffffu, ss, o);
        float inv = 1.f / fmaxf(sqrtf(ss), L2_EPS);
        int g = batch[n];
        if (g != cur) {
            if (cur >= 0) {
                #pragma unroll
                for (int q = 0; q < 4; q++) atomicAdd(&g_pool[cur * 128 + lane * 4 + q], acc[q]);
                if (lane == 0) atomicAdd(&g_gcnt[cur], cnt);
            }
            cur = g; cnt = 1;
            #pragma unroll
            for (int q = 0; q < 4; q++) acc[q] = y[q] * inv;
        } else {
            cnt++;
            #pragma unroll
            for (int q = 0; q < 4; q++) acc[q] += y[q] * inv;
        }
    }
    if (cur >= 0) {
        #pragma unroll
        for (int q = 0; q < 4; q++) atomicAdd(&g_pool[cur * 128 + lane * 4 + q], acc[q]);
        if (lane == 0) atomicAdd(&g_gcnt[cur], cnt);
    }
}

// ---------------- MLP head: one block per graph ---------------------------------
__global__ __launch_bounds__(256) void k_mlp(const float* __restrict__ fc1w, const float* __restrict__ fc1b,
                                             const float* __restrict__ fc2w, const float* __restrict__ fc2b,
                                             const float* __restrict__ ow,  const float* __restrict__ ob,
                                             float* __restrict__ out) {
    int g = blockIdx.x;
    int t = threadIdx.x;
    __shared__ float sg[128], s1[256], s2[128], red[256];
    float invc = 1.f / fmaxf((float)g_gcnt[g], 1.f);
    if (t < 128) sg[t] = g_pool[g * 128 + t] * invc;
    __syncthreads();
    float s = fc1b[t];
    #pragma unroll 8
    for (int k = 0; k < 128; k++) s += sg[k] * fc1w[k * 256 + t];
    s1[t] = fmaxf(s, 0.f);
    __syncthreads();
    if (t < 128) {
        float s2v = fc2b[t];
        #pragma unroll 8
        for (int k = 0; k < 256; k++) s2v += s1[k] * fc2w[k * 128 + t];
        s2[t] = fmaxf(s2v, 0.f);
    }
    __syncthreads();
    red[t] = (t < 128) ? s2[t] * ow[t] : 0.f;
    __syncthreads();
    for (int o = 128; o > 0; o >>= 1) {
        if (t < o) red[t] += red[t + o];
        __syncthreads();
    }
    if (t == 0) out[g] = red[0] + ob[0];
}

// =============================================================================
extern "C" void kernel_launch(void* const* d_in, const int* in_sizes, int n_in,
                              void* d_out, int out_size) {
    const float* x      = (const float*)d_in[0];
    const int*   ei     = (const int*)  d_in[1];
    const int*   etype  = (const int*)  d_in[2];
    const int*   batch  = (const int*)  d_in[3];
    const float* emb    = (const float*)d_in[4];
    const float* Wrel   = (const float*)d_in[5];
    const float* Wroot  = (const float*)d_in[6];
    const float* cbias  = (const float*)d_in[7];
    const float* gamma  = (const float*)d_in[8];
    const float* beta   = (const float*)d_in[9];
    const float* pa     = (const float*)d_in[10];
    const float* fc1w   = (const float*)d_in[11];
    const float* fc1b   = (const float*)d_in[12];
    const float* fc2w   = (const float*)d_in[13];
    const float* fc2b   = (const float*)d_in[14];
    const float* ow     = (const float*)d_in[15];
    const float* ob     = (const float*)d_in[16];
    float* out = (float*)d_out;

    const int TB = 256;
    const int GEMM_SMEM = 4 * 128 * AKS * 2 + 256 * 4;   // A+B stages (fp16) + stats

    static cudaStream_t s1 = nullptr;
    static cudaEvent_t evStart, evW;
    if (!s1) {
        cudaFuncSetAttribute(k_gemm_f16, cudaFuncAttributeMaxDynamicSharedMemorySize, GEMM_SMEM);
        cudaStreamCreateWithFlags(&s1, cudaStreamNonBlocking);
        cudaEventCreateWithFlags(&evStart, cudaEventDisableTiming);
        cudaEventCreateWithFlags(&evW, cudaEventDisableTiming);
    }

    // ---- fork: weights on s1 (independent of graph structure) ----
    cudaEventRecord(evStart, 0);
    cudaStreamWaitEvent(s1, evStart, 0);
    k_weights<<<(N_TYPES * WCOLS + WCOLS * 128 + TB - 1) / TB, TB, 0, s1>>>(emb, Wrel, Wroot, cbias);
    cudaEventRecord(evW, s1);

    // ---- prep + graph structure (default stream) ----
    k_prep<<<(N_NODES * 4 + TB - 1) / TB, TB>>>(x);
    k_count<<<(N_EDGES + TB - 1) / TB, TB>>>(ei, etype);
    k_scan1<<<NB_SCAN, 256>>>();
    k_scan2<<<1, 512>>>();
    k_scan3<<<(N_NODES + TB - 1) / TB, TB>>>();
    k_fill<<<(N_EDGES + TB - 1) / TB, TB>>>(ei, etype);

    // join weights before layer 0 (agg0 needs g_T0)
    cudaStreamWaitEvent(0, evW, 0);

    const int nodeWarpBlocks = (N_NODES * 32 + TB - 1) / TB;
    const int npwBlocks = ((N_NODES + 15) / 16 * 32 + TB - 1) / TB;

    // ---- layer 0 (table shortcut; f32 stats source, fp16 mirror out) ----
    k_agg0<<<nodeWarpBlocks, TB>>>();
    k_bnstats0<<<512, 128>>>();
    k_bnapply0<<<nodeWarpBlocks, TB>>>(gamma, beta, pa);

    // ---- layer 1: fp16 half-warp gather → fp16 G, then fp16 GEMM (fused stats) --
    k_gather1<<<nodeWarpBlocks, TB>>>();
    k_gemm_f16<<<(N_NODES + 127) / 128, 256, GEMM_SMEM>>>(cbias + 128);

    // ---- fused BN+PReLU+L2norm+pool, then MLP ----
    k_bnpool<<<npwBlocks, TB>>>(batch, gamma + 128, beta + 128, pa);
    k_mlp<<<N_GRAPHS, 256>>>(fc1w, fc1b, fc2w, fc2b, ow, ob, out);
}